// round 1
// baseline (speedup 1.0000x reference)
#include <cuda_runtime.h>

#define B_   4
#define T_   2048
#define C_   1024
#define H_   16
#define DH_  64
#define C3_  3072
#define QPAD 68

// Scratch (no cudaMalloc allowed)
__device__ float g_qkv[(size_t)B_ * T_ * C3_];   // [B*T, 3C]
__device__ float g_attn[(size_t)B_ * T_ * C_];   // [B*T, C] concat-head attention output

// ---------------------------------------------------------------------------
// Classic 128x128x8 SGEMM, 256 threads, 8x8 micro-tile per thread.
// Frags split into [ty*4 .. +3] and [ty*4+64 .. +3] to keep LDS conflict-free.
// Requires M%128==0, N%128==0, K%8==0 (true for all shapes here).
// ---------------------------------------------------------------------------
__global__ void __launch_bounds__(256) sgemm128(const float* __restrict__ A,
                                                const float* __restrict__ Bm,
                                                float* __restrict__ Cm,
                                                int M, int N, int K)
{
    __shared__ float As[8][128];
    __shared__ float Bs[8][128];

    const int tid  = threadIdx.x;
    const int bx   = blockIdx.x * 128;
    const int by   = blockIdx.y * 128;
    const int tx   = tid & 15;
    const int ty   = tid >> 4;

    // Global-load assignments
    const int arow = tid >> 1;            // 0..127
    const int acol = (tid & 1) * 4;       // 0 or 4
    const int brow = tid >> 5;            // 0..7
    const int bcol = (tid & 31) * 4;      // 0..124

    float acc[8][8];
#pragma unroll
    for (int i = 0; i < 8; i++)
#pragma unroll
        for (int j = 0; j < 8; j++) acc[i][j] = 0.f;

    const float* Ap = A  + (size_t)(by + arow) * K + acol;
    const float* Bp = Bm + (size_t)brow * N + bx + bcol;

    for (int k0 = 0; k0 < K; k0 += 8) {
        float4 av = *(const float4*)(Ap + k0);
        float4 bv = *(const float4*)(Bp + (size_t)k0 * N);
        As[acol + 0][arow] = av.x;
        As[acol + 1][arow] = av.y;
        As[acol + 2][arow] = av.z;
        As[acol + 3][arow] = av.w;
        *(float4*)&Bs[brow][bcol] = bv;
        __syncthreads();

#pragma unroll
        for (int kk = 0; kk < 8; kk++) {
            float a[8], b[8];
            *(float4*)(a)     = *(const float4*)&As[kk][ty * 4];
            *(float4*)(a + 4) = *(const float4*)&As[kk][ty * 4 + 64];
            *(float4*)(b)     = *(const float4*)&Bs[kk][tx * 4];
            *(float4*)(b + 4) = *(const float4*)&Bs[kk][tx * 4 + 64];
#pragma unroll
            for (int i = 0; i < 8; i++)
#pragma unroll
                for (int j = 0; j < 8; j++)
                    acc[i][j] += a[i] * b[j];
        }
        __syncthreads();
    }

#pragma unroll
    for (int i = 0; i < 8; i++) {
        int r = by + ((i < 4) ? (ty * 4 + i) : (64 + ty * 4 + i - 4));
        float* crow = Cm + (size_t)r * N + bx;
        *(float4*)(crow + tx * 4)      = make_float4(acc[i][0], acc[i][1], acc[i][2], acc[i][3]);
        *(float4*)(crow + 64 + tx * 4) = make_float4(acc[i][4], acc[i][5], acc[i][6], acc[i][7]);
    }
}

// ---------------------------------------------------------------------------
// Flash-attention (fp32) with causal mask + ALiBi bias.
// Block = (qtile=64 rows) x (b,h). 256 threads: qrow = tid&63, sub = tid>>6.
// - K/V smem reads are warp-uniform (broadcast, 1 wavefront).
// - Q smem stride 68 -> conflict-free LDS.128 across the 32 qrow lanes.
// - p stored transposed [key][qrow] stride 64 -> conflict-free both ways.
// - Cross-warp row reductions via red_m / red_l in smem.
// ---------------------------------------------------------------------------
__global__ void __launch_bounds__(256) attn_kernel(const float* __restrict__ qkv,
                                                   float* __restrict__ out)
{
    extern __shared__ float sm[];
    float* q_s   = sm;                   // 64 * 68
    float* k_s   = q_s + 64 * QPAD;      // 64 * 64
    float* v_s   = k_s + 64 * 64;        // 64 * 64
    float* p_s   = v_s + 64 * 64;        // 64 * 64  [key][qrow]
    float* red_m = p_s + 64 * 64;        // 256
    float* red_l = red_m + 256;          // 256

    const int b    = blockIdx.z;
    const int h    = blockIdx.y;
    const int qt   = blockIdx.x;
    const int q0   = qt * 64;
    const int tid  = threadIdx.x;
    const int qrow = tid & 63;
    const int sub  = tid >> 6;

    const float slope     = exp2f(-0.5f * (float)(h + 1));  // 1/((2^8)^((h+1)/16)) = 2^(-(h+1)/2)
    const float inv_scale = 1.0f / 32.0f;                   // 1/sqrt(C), C=1024
    const size_t bbase    = (size_t)b * T_ * C3_;
    const int hoff        = h * DH_;

    // Load Q tile: 64 rows x 64 floats = 1024 float4, coalesced
    for (int i = tid; i < 1024; i += 256) {
        int r = i >> 4, c = (i & 15) * 4;
        *(float4*)(q_s + r * QPAD + c) =
            *(const float4*)(qkv + bbase + (size_t)(q0 + r) * C3_ + hoff + c);
    }

    float m = -1e30f, l = 0.f;
    float acc[16];
#pragma unroll
    for (int i = 0; i < 16; i++) acc[i] = 0.f;

    const int gq = q0 + qrow;

    for (int kt = 0; kt <= qt; kt++) {
        __syncthreads();   // protect k_s/v_s (prev AV) and p_s/red (prev tile)
        const int k0 = kt * 64;
        for (int i = tid; i < 1024; i += 256) {
            int r = i >> 4, c = (i & 15) * 4;
            const float* src = qkv + bbase + (size_t)(k0 + r) * C3_ + hoff + c;
            *(float4*)(k_s + r * 64 + c) = *(const float4*)(src + C_);
            *(float4*)(v_s + r * 64 + c) = *(const float4*)(src + 2 * C_);
        }
        __syncthreads();

        // --- scores: this thread computes row qrow vs keys [sub*16 .. sub*16+15]
        float s[16];
#pragma unroll
        for (int j = 0; j < 16; j++) s[j] = 0.f;
        const float* qr = q_s + qrow * QPAD;
        const float* kb = k_s + sub * 16 * 64;
#pragma unroll 4
        for (int d4 = 0; d4 < 16; d4++) {
            float4 q4 = *(const float4*)(qr + d4 * 4);
#pragma unroll
            for (int j = 0; j < 16; j++) {
                float4 k4 = *(const float4*)(kb + j * 64 + d4 * 4);
                s[j] += q4.x * k4.x;
                s[j] += q4.y * k4.y;
                s[j] += q4.z * k4.z;
                s[j] += q4.w * k4.w;
            }
        }

        // scale + ALiBi + causal mask, local max
        float mloc = -1e30f;
#pragma unroll
        for (int j = 0; j < 16; j++) {
            int gk = k0 + sub * 16 + j;
            float v = s[j] * inv_scale + slope * (float)(gk - gq);
            s[j] = (gk <= gq) ? v : -1e30f;
            mloc = fmaxf(mloc, s[j]);
        }
        red_m[sub * 64 + qrow] = mloc;
        __syncthreads();
        float mnew = fmaxf(m, fmaxf(fmaxf(red_m[qrow], red_m[64 + qrow]),
                                    fmaxf(red_m[128 + qrow], red_m[192 + qrow])));
        float corr = __expf(m - mnew);

        float lloc = 0.f;
#pragma unroll
        for (int j = 0; j < 16; j++) {
            float p = __expf(s[j] - mnew);
            p_s[(sub * 16 + j) * 64 + qrow] = p;
            lloc += p;
        }
        red_l[sub * 64 + qrow] = lloc;
        __syncthreads();   // also makes p_s visible to all warps
        l = l * corr + (red_l[qrow] + red_l[64 + qrow])
                     + (red_l[128 + qrow] + red_l[192 + qrow]);
        m = mnew;
#pragma unroll
        for (int i = 0; i < 16; i++) acc[i] *= corr;

        // --- AV: this thread accumulates dims [sub*16 .. +15] for row qrow
        const float* vb = v_s + sub * 16;
#pragma unroll 8
        for (int j = 0; j < 64; j++) {
            float  p  = p_s[j * 64 + qrow];
            float4 v0 = *(const float4*)(vb + j * 64);
            float4 v1 = *(const float4*)(vb + j * 64 + 4);
            float4 v2 = *(const float4*)(vb + j * 64 + 8);
            float4 v3 = *(const float4*)(vb + j * 64 + 12);
            acc[0]  += p * v0.x;  acc[1]  += p * v0.y;  acc[2]  += p * v0.z;  acc[3]  += p * v0.w;
            acc[4]  += p * v1.x;  acc[5]  += p * v1.y;  acc[6]  += p * v1.z;  acc[7]  += p * v1.w;
            acc[8]  += p * v2.x;  acc[9]  += p * v2.y;  acc[10] += p * v2.z;  acc[11] += p * v2.w;
            acc[12] += p * v3.x;  acc[13] += p * v3.y;  acc[14] += p * v3.z;  acc[15] += p * v3.w;
        }
    }

    const float invl = 1.0f / l;
    float* op = out + (size_t)(b * T_ + gq) * C_ + hoff + sub * 16;
#pragma unroll
    for (int i = 0; i < 16; i += 4)
        *(float4*)(op + i) = make_float4(acc[i] * invl, acc[i + 1] * invl,
                                         acc[i + 2] * invl, acc[i + 3] * invl);
}

// ---------------------------------------------------------------------------
extern "C" void kernel_launch(void* const* d_in, const int* in_sizes, int n_in,
                              void* d_out, int out_size)
{
    const float* x     = (const float*)d_in[0];
    const float* w_qkv = (const float*)d_in[1];
    const float* w_o   = (const float*)d_in[2];
    float* out = (float*)d_out;

    float *qkv, *attn;
    cudaGetSymbolAddress((void**)&qkv,  g_qkv);
    cudaGetSymbolAddress((void**)&attn, g_attn);

    const int SMEM_ATTN = (64 * QPAD + 3 * 64 * 64 + 512) * (int)sizeof(float); // 68608 B
    cudaFuncSetAttribute(attn_kernel, cudaFuncAttributeMaxDynamicSharedMemorySize, SMEM_ATTN);

    // 1) qkv = x @ w_qkv   [8192,1024] x [1024,3072]
    dim3 g1(C3_ / 128, (B_ * T_) / 128);
    sgemm128<<<g1, 256>>>(x, w_qkv, qkv, B_ * T_, C3_, C_);

    // 2) flash attention with ALiBi + causal
    dim3 g2(T_ / 64, H_, B_);
    attn_kernel<<<g2, 256, SMEM_ATTN>>>(qkv, attn);

    // 3) out = attn @ w_o  [8192,1024] x [1024,1024]
    dim3 g3(C_ / 128, (B_ * T_) / 128);
    sgemm128<<<g3, 256>>>(attn, w_o, out, B_ * T_, C_, C_);
}

// round 4
// speedup vs baseline: 1.2922x; 1.2922x over previous
#include <cuda_runtime.h>
#include <cuda_bf16.h>
#include <cstdint>

#define B_   4
#define T_   2048
#define C_   1024
#define H_   16
#define DH_  64
#define C3_  3072
#define QPAD 68
#define M_   (B_*T_)      // 8192 rows
#define K_   1024

// ---------------------------------------------------------------------------
// Scratch (no cudaMalloc allowed). ahi/alo alias xhi/xlo (disjoint liveness:
// xhi/xlo dead after GEMM-1; ahi/alo written only after attn_kernel retires).
// ---------------------------------------------------------------------------
__device__ float g_qkv[(size_t)M_ * C3_];    // [M, 3C] fp32
__device__ float g_attn[(size_t)M_ * C_];    // [M, C]  fp32
__device__ __nv_bfloat16 g_xhi[(size_t)M_ * C_];
__device__ __nv_bfloat16 g_xlo[(size_t)M_ * C_];
__device__ __nv_bfloat16 g_wqhi[(size_t)C3_ * C_];   // W_qkv^T  [N=3072][K=1024]
__device__ __nv_bfloat16 g_wqlo[(size_t)C3_ * C_];
__device__ __nv_bfloat16 g_wohi[(size_t)C_ * C_];    // W_o^T    [N=1024][K=1024]
__device__ __nv_bfloat16 g_wolo[(size_t)C_ * C_];

// ---------------------------------------------------------------------------
// Helpers (all plain compute_103-legal: ldmatrix / mma.sync / cp.async)
// ---------------------------------------------------------------------------
__device__ __forceinline__ uint32_t smem_u32(const void* p) {
    uint32_t a;
    asm("{ .reg .u64 t; cvta.to.shared.u64 t, %1; cvt.u32.u64 %0, t; }" : "=r"(a) : "l"(p));
    return a;
}
__device__ __forceinline__ void cpa16(uint32_t dst, const void* src) {
    asm volatile("cp.async.cg.shared.global [%0], [%1], 16;" :: "r"(dst), "l"(src));
}
__device__ __forceinline__ void ldm4(uint32_t* r, uint32_t addr) {
    asm volatile("ldmatrix.sync.aligned.m8n8.x4.shared.b16 {%0,%1,%2,%3}, [%4];"
                 : "=r"(r[0]), "=r"(r[1]), "=r"(r[2]), "=r"(r[3]) : "r"(addr));
}
__device__ __forceinline__ void mma16816(float* d, const uint32_t* a, const uint32_t* b) {
    asm volatile("mma.sync.aligned.m16n8k16.row.col.f32.bf16.bf16.f32 "
                 "{%0,%1,%2,%3}, {%4,%5,%6,%7}, {%8,%9}, {%0,%1,%2,%3};"
                 : "+f"(d[0]), "+f"(d[1]), "+f"(d[2]), "+f"(d[3])
                 : "r"(a[0]), "r"(a[1]), "r"(a[2]), "r"(a[3]), "r"(b[0]), "r"(b[1]));
}

// ---------------------------------------------------------------------------
// Split fp32 -> bf16 hi/lo
// ---------------------------------------------------------------------------
__global__ void split_f32(const float* __restrict__ x,
                          __nv_bfloat16* __restrict__ hi,
                          __nv_bfloat16* __restrict__ lo, int n)
{
    int i = blockIdx.x * blockDim.x + threadIdx.x;
    if (i < n) {
        float v = x[i];
        __nv_bfloat16 h = __float2bfloat16(v);
        hi[i] = h;
        lo[i] = __float2bfloat16(v - __bfloat162float(h));
    }
}

// Transpose + split: W[K][N] fp32 -> Thi/Tlo[N][K] bf16
__global__ void splitT_f32(const float* __restrict__ W,
                           __nv_bfloat16* __restrict__ Thi,
                           __nv_bfloat16* __restrict__ Tlo, int K, int N)
{
    __shared__ float t[32][33];
    int n0 = blockIdx.x * 32, k0 = blockIdx.y * 32;
    int tx = threadIdx.x, ty = threadIdx.y;   // 32 x 8
    for (int r = ty; r < 32; r += 8)
        t[r][tx] = W[(size_t)(k0 + r) * N + n0 + tx];
    __syncthreads();
    for (int r = ty; r < 32; r += 8) {
        float v = t[tx][r];
        __nv_bfloat16 h = __float2bfloat16(v);
        size_t o = (size_t)(n0 + r) * K + k0 + tx;
        Thi[o] = h;
        Tlo[o] = __float2bfloat16(v - __bfloat162float(h));
    }
}

// ---------------------------------------------------------------------------
// mma.sync bf16x3 GEMM:  C[M,N] = A[M,K] * B^T   (A,B stored [rows][K] bf16)
// CTA 128x128, BK=32, 3-stage cp.async pipeline.
// SMEM layout: 8x8-bf16 blocks (128B contiguous) indexed [k8][row8] ->
// every ldmatrix.x4 covers whole 128B lines => conflict-free.
// ---------------------------------------------------------------------------
#define BKSLAB     32
#define OPB        8192                 // one operand per stage: 128 rows x 32k x 2B
#define STAGEB     (4 * OPB)            // AH, AL, BH, BL
#define GSTAGES    3
#define GEMM_SMEM  (GSTAGES * STAGEB)   // 98304 B

__global__ void __launch_bounds__(256) gemm_mma(
    const __nv_bfloat16* __restrict__ Ahi, const __nv_bfloat16* __restrict__ Alo,
    const __nv_bfloat16* __restrict__ Bhi, const __nv_bfloat16* __restrict__ Blo,
    float* __restrict__ Cg, int N)
{
    extern __shared__ char smem[];
    const uint32_t sb = smem_u32(smem);
    const int tid  = threadIdx.x;
    const int m0   = blockIdx.y * 128;
    const int n0   = blockIdx.x * 128;
    const int wid  = tid >> 5, lane = tid & 31;
    const int warp_m = (wid & 1) * 64;
    const int warp_n = (wid >> 1) * 32;

    const __nv_bfloat16* pAh = Ahi + (size_t)m0 * K_;
    const __nv_bfloat16* pAl = Alo + (size_t)m0 * K_;
    const __nv_bfloat16* pBh = Bhi + (size_t)n0 * K_;
    const __nv_bfloat16* pBl = Blo + (size_t)n0 * K_;

    auto load_stage = [&](int it, int slot) {
        const uint32_t st = sb + slot * STAGEB;
        const int kb = it * BKSLAB;
#pragma unroll
        for (int i = 0; i < 8; i++) {                 // op = i>>1 (compile-time)
            const __nv_bfloat16* base = (i < 2) ? pAh : (i < 4) ? pAl : (i < 6) ? pBh : pBl;
            int w   = ((i & 1) << 8) + tid;           // 0..511 within operand
            int row = w >> 2;                         // 0..127
            int k8  = w & 3;                          // 0..3
            const void* src = base + (size_t)row * K_ + kb + k8 * 8;
            uint32_t dst = st + (i >> 1) * OPB + (k8 * 16 + (row >> 3)) * 128 + (row & 7) * 16;
            cpa16(dst, src);
        }
        asm volatile("cp.async.commit_group;" ::: "memory");
    };

    float acc[4][4][4];
#pragma unroll
    for (int a = 0; a < 4; a++)
#pragma unroll
        for (int b = 0; b < 4; b++)
#pragma unroll
            for (int c = 0; c < 4; c++) acc[a][b][c] = 0.f;

    // ldmatrix lane address components
    const int mA  = warp_m + (lane & 15);
    const int mA8 = mA >> 3, mA7 = (mA & 7) * 16;
    const int k8A = lane >> 4;                        // 0/1
    const int nB  = warp_n + ((lane >> 4) << 3) + (lane & 7);
    const int nB8 = nB >> 3, nB7 = (nB & 7) * 16;
    const int k8B = (lane >> 3) & 1;                  // 0/1

    load_stage(0, 0);
    load_stage(1, 1);

    const int NIT = K_ / BKSLAB;                      // 32
    for (int it = 0; it < NIT; it++) {
        if (it + 1 < NIT) asm volatile("cp.async.wait_group 1;" ::: "memory");
        else              asm volatile("cp.async.wait_group 0;" ::: "memory");
        __syncthreads();
        if (it + 2 < NIT) load_stage(it + 2, (it + 2) % GSTAGES);

        const uint32_t st = sb + (it % GSTAGES) * STAGEB;
        const uint32_t AH = st, AL = st + OPB, BH = st + 2 * OPB, BL = st + 3 * OPB;

#pragma unroll
        for (int ks = 0; ks < 2; ks++) {
            uint32_t ah[4][4], al[4][4], bb[4][2];
            const int kA = (ks * 2 + k8A) * 2048;     // k8*16*128
            const int kB = (ks * 2 + k8B) * 2048;
#pragma unroll
            for (int mt = 0; mt < 4; mt++)
                ldm4(ah[mt], AH + kA + (mA8 + mt * 2) * 128 + mA7);
#pragma unroll
            for (int j = 0; j < 2; j++)
                ldm4(&bb[j * 2][0], BH + kB + (nB8 + j * 2) * 128 + nB7);
#pragma unroll
            for (int mt = 0; mt < 4; mt++)
#pragma unroll
                for (int nt = 0; nt < 4; nt++) mma16816(acc[mt][nt], ah[mt], bb[nt]);
#pragma unroll
            for (int mt = 0; mt < 4; mt++)
                ldm4(al[mt], AL + kA + (mA8 + mt * 2) * 128 + mA7);
#pragma unroll
            for (int mt = 0; mt < 4; mt++)
#pragma unroll
                for (int nt = 0; nt < 4; nt++) mma16816(acc[mt][nt], al[mt], bb[nt]);
#pragma unroll
            for (int j = 0; j < 2; j++)
                ldm4(&bb[j * 2][0], BL + kB + (nB8 + j * 2) * 128 + nB7);
#pragma unroll
            for (int mt = 0; mt < 4; mt++)
#pragma unroll
                for (int nt = 0; nt < 4; nt++) mma16816(acc[mt][nt], ah[mt], bb[nt]);
        }
        __syncthreads();
    }

    // Epilogue: thread holds C[r][c], r = warp_m+mt*16+lane/4 (+8), c = warp_n+nt*8+(lane%4)*2
    const int r0 = m0 + warp_m + (lane >> 2);
    const int c0 = n0 + warp_n + (lane & 3) * 2;
#pragma unroll
    for (int mt = 0; mt < 4; mt++) {
#pragma unroll
        for (int nt = 0; nt < 4; nt++) {
            float* p = Cg + (size_t)(r0 + mt * 16) * N + c0 + nt * 8;
            *(float2*)p                    = make_float2(acc[mt][nt][0], acc[mt][nt][1]);
            *(float2*)(p + (size_t)8 * N)  = make_float2(acc[mt][nt][2], acc[mt][nt][3]);
        }
    }
}

// ---------------------------------------------------------------------------
// Flash-attention (fp32) with causal mask + ALiBi bias (unchanged, known good)
// ---------------------------------------------------------------------------
__global__ void __launch_bounds__(256) attn_kernel(const float* __restrict__ qkv,
                                                   float* __restrict__ out)
{
    extern __shared__ float sm[];
    float* q_s   = sm;                   // 64 * 68
    float* k_s   = q_s + 64 * QPAD;      // 64 * 64
    float* v_s   = k_s + 64 * 64;        // 64 * 64
    float* p_s   = v_s + 64 * 64;        // 64 * 64  [key][qrow]
    float* red_m = p_s + 64 * 64;        // 256
    float* red_l = red_m + 256;          // 256

    const int b    = blockIdx.z;
    const int h    = blockIdx.y;
    const int qt   = blockIdx.x;
    const int q0   = qt * 64;
    const int tid  = threadIdx.x;
    const int qrow = tid & 63;
    const int sub  = tid >> 6;

    const float slope     = exp2f(-0.5f * (float)(h + 1));
    const float inv_scale = 1.0f / 32.0f;
    const size_t bbase    = (size_t)b * T_ * C3_;
    const int hoff        = h * DH_;

    for (int i = tid; i < 1024; i += 256) {
        int r = i >> 4, c = (i & 15) * 4;
        *(float4*)(q_s + r * QPAD + c) =
            *(const float4*)(qkv + bbase + (size_t)(q0 + r) * C3_ + hoff + c);
    }

    float m = -1e30f, l = 0.f;
    float acc[16];
#pragma unroll
    for (int i = 0; i < 16; i++) acc[i] = 0.f;

    const int gq = q0 + qrow;

    for (int kt = 0; kt <= qt; kt++) {
        __syncthreads();
        const int k0 = kt * 64;
        for (int i = tid; i < 1024; i += 256) {
            int r = i >> 4, c = (i & 15) * 4;
            const float* src = qkv + bbase + (size_t)(k0 + r) * C3_ + hoff + c;
            *(float4*)(k_s + r * 64 + c) = *(const float4*)(src + C_);
            *(float4*)(v_s + r * 64 + c) = *(const float4*)(src + 2 * C_);
        }
        __syncthreads();

        float s[16];
#pragma unroll
        for (int j = 0; j < 16; j++) s[j] = 0.f;
        const float* qr = q_s + qrow * QPAD;
        const float* kb = k_s + sub * 16 * 64;
#pragma unroll 4
        for (int d4 = 0; d4 < 16; d4++) {
            float4 q4 = *(const float4*)(qr + d4 * 4);
#pragma unroll
            for (int j = 0; j < 16; j++) {
                float4 k4 = *(const float4*)(kb + j * 64 + d4 * 4);
                s[j] += q4.x * k4.x;
                s[j] += q4.y * k4.y;
                s[j] += q4.z * k4.z;
                s[j] += q4.w * k4.w;
            }
        }

        float mloc = -1e30f;
#pragma unroll
        for (int j = 0; j < 16; j++) {
            int gk = k0 + sub * 16 + j;
            float v = s[j] * inv_scale + slope * (float)(gk - gq);
            s[j] = (gk <= gq) ? v : -1e30f;
            mloc = fmaxf(mloc, s[j]);
        }
        red_m[sub * 64 + qrow] = mloc;
        __syncthreads();
        float mnew = fmaxf(m, fmaxf(fmaxf(red_m[qrow], red_m[64 + qrow]),
                                    fmaxf(red_m[128 + qrow], red_m[192 + qrow])));
        float corr = __expf(m - mnew);

        float lloc = 0.f;
#pragma unroll
        for (int j = 0; j < 16; j++) {
            float p = __expf(s[j] - mnew);
            p_s[(sub * 16 + j) * 64 + qrow] = p;
            lloc += p;
        }
        red_l[sub * 64 + qrow] = lloc;
        __syncthreads();
        l = l * corr + (red_l[qrow] + red_l[64 + qrow])
                     + (red_l[128 + qrow] + red_l[192 + qrow]);
        m = mnew;
#pragma unroll
        for (int i = 0; i < 16; i++) acc[i] *= corr;

        const float* vb = v_s + sub * 16;
#pragma unroll 8
        for (int j = 0; j < 64; j++) {
            float  p  = p_s[j * 64 + qrow];
            float4 v0 = *(const float4*)(vb + j * 64);
            float4 v1 = *(const float4*)(vb + j * 64 + 4);
            float4 v2 = *(const float4*)(vb + j * 64 + 8);
            float4 v3 = *(const float4*)(vb + j * 64 + 12);
            acc[0]  += p * v0.x;  acc[1]  += p * v0.y;  acc[2]  += p * v0.z;  acc[3]  += p * v0.w;
            acc[4]  += p * v1.x;  acc[5]  += p * v1.y;  acc[6]  += p * v1.z;  acc[7]  += p * v1.w;
            acc[8]  += p * v2.x;  acc[9]  += p * v2.y;  acc[10] += p * v2.z;  acc[11] += p * v2.w;
            acc[12] += p * v3.x;  acc[13] += p * v3.y;  acc[14] += p * v3.z;  acc[15] += p * v3.w;
        }
    }

    const float invl = 1.0f / l;
    float* op = out + (size_t)(b * T_ + gq) * C_ + hoff + sub * 16;
#pragma unroll
    for (int i = 0; i < 16; i += 4)
        *(float4*)(op + i) = make_float4(acc[i] * invl, acc[i + 1] * invl,
                                         acc[i + 2] * invl, acc[i + 3] * invl);
}

// ---------------------------------------------------------------------------
extern "C" void kernel_launch(void* const* d_in, const int* in_sizes, int n_in,
                              void* d_out, int out_size)
{
    const float* x     = (const float*)d_in[0];
    const float* w_qkv = (const float*)d_in[1];
    const float* w_o   = (const float*)d_in[2];
    float* out = (float*)d_out;

    float *qkv, *attn;
    __nv_bfloat16 *xhi, *xlo, *wqhi, *wqlo, *wohi, *wolo;
    cudaGetSymbolAddress((void**)&qkv,  g_qkv);
    cudaGetSymbolAddress((void**)&attn, g_attn);
    cudaGetSymbolAddress((void**)&xhi,  g_xhi);
    cudaGetSymbolAddress((void**)&xlo,  g_xlo);
    cudaGetSymbolAddress((void**)&wqhi, g_wqhi);
    cudaGetSymbolAddress((void**)&wqlo, g_wqlo);
    cudaGetSymbolAddress((void**)&wohi, g_wohi);
    cudaGetSymbolAddress((void**)&wolo, g_wolo);

    const int SMEM_ATTN = (64 * QPAD + 3 * 64 * 64 + 512) * (int)sizeof(float);
    cudaFuncSetAttribute(attn_kernel, cudaFuncAttributeMaxDynamicSharedMemorySize, SMEM_ATTN);
    cudaFuncSetAttribute(gemm_mma,    cudaFuncAttributeMaxDynamicSharedMemorySize, GEMM_SMEM);

    // 0) splits / transposed-split weights
    split_f32<<<(M_ * C_ + 255) / 256, 256>>>(x, xhi, xlo, M_ * C_);
    splitT_f32<<<dim3(C3_ / 32, C_ / 32), dim3(32, 8)>>>(w_qkv, wqhi, wqlo, C_, C3_);
    splitT_f32<<<dim3(C_ / 32,  C_ / 32), dim3(32, 8)>>>(w_o,   wohi, wolo, C_, C_);

    // 1) qkv = x @ w_qkv  (tensor cores, split-bf16 x3)
    gemm_mma<<<dim3(C3_ / 128, M_ / 128), 256, GEMM_SMEM>>>(xhi, xlo, wqhi, wqlo, qkv, C3_);

    // 2) flash attention with ALiBi + causal (fp32)
    dim3 g2(T_ / 64, H_, B_);
    attn_kernel<<<g2, 256, SMEM_ATTN>>>(qkv, attn);

    // 3) out = attn @ w_o  (tensor cores, split-bf16 x3; reuse x-split buffers)
    split_f32<<<(M_ * C_ + 255) / 256, 256>>>(attn, xhi, xlo, M_ * C_);
    gemm_mma<<<dim3(C_ / 128, M_ / 128), 256, GEMM_SMEM>>>(xhi, xlo, wohi, wolo, out, C_);
}

// round 5
// speedup vs baseline: 1.9671x; 1.5223x over previous
#include <cuda_runtime.h>
#include <cuda_bf16.h>
#include <cstdint>

#define B_   4
#define T_   2048
#define C_   1024
#define H_   16
#define DH_  64
#define C3_  3072
#define M_   (B_*T_)      // 8192 rows
#define K_   1024

// ---------------------------------------------------------------------------
// Scratch (no cudaMalloc). xhi/xlo are reused for the attention bf16 output
// (x-split dead after GEMM-1; attention writes only after it retires).
// ---------------------------------------------------------------------------
__device__ __nv_bfloat16 g_xhi[(size_t)M_ * C_];
__device__ __nv_bfloat16 g_xlo[(size_t)M_ * C_];
__device__ __nv_bfloat16 g_qkvh[(size_t)M_ * C3_];   // qkv hi  [M][3C]
__device__ __nv_bfloat16 g_qkvl[(size_t)M_ * C3_];   // qkv lo
__device__ __nv_bfloat16 g_wqhi[(size_t)C3_ * C_];   // W_qkv^T [3072][1024]
__device__ __nv_bfloat16 g_wqlo[(size_t)C3_ * C_];
__device__ __nv_bfloat16 g_wohi[(size_t)C_ * C_];    // W_o^T   [1024][1024]
__device__ __nv_bfloat16 g_wolo[(size_t)C_ * C_];

// ---------------------------------------------------------------------------
// Helpers (plain compute_103-legal)
// ---------------------------------------------------------------------------
__device__ __forceinline__ uint32_t smem_u32(const void* p) {
    uint32_t a;
    asm("{ .reg .u64 t; cvta.to.shared.u64 t, %1; cvt.u32.u64 %0, t; }" : "=r"(a) : "l"(p));
    return a;
}
__device__ __forceinline__ void cpa16(uint32_t dst, const void* src) {
    asm volatile("cp.async.cg.shared.global [%0], [%1], 16;" :: "r"(dst), "l"(src));
}
__device__ __forceinline__ void ldm4(uint32_t* r, uint32_t addr) {
    asm volatile("ldmatrix.sync.aligned.m8n8.x4.shared.b16 {%0,%1,%2,%3}, [%4];"
                 : "=r"(r[0]), "=r"(r[1]), "=r"(r[2]), "=r"(r[3]) : "r"(addr));
}
__device__ __forceinline__ void ldm4t(uint32_t* r, uint32_t addr) {
    asm volatile("ldmatrix.sync.aligned.m8n8.x4.trans.shared.b16 {%0,%1,%2,%3}, [%4];"
                 : "=r"(r[0]), "=r"(r[1]), "=r"(r[2]), "=r"(r[3]) : "r"(addr));
}
__device__ __forceinline__ void mma16816(float* d, const uint32_t* a, const uint32_t* b) {
    asm volatile("mma.sync.aligned.m16n8k16.row.col.f32.bf16.bf16.f32 "
                 "{%0,%1,%2,%3}, {%4,%5,%6,%7}, {%8,%9}, {%0,%1,%2,%3};"
                 : "+f"(d[0]), "+f"(d[1]), "+f"(d[2]), "+f"(d[3])
                 : "r"(a[0]), "r"(a[1]), "r"(a[2]), "r"(a[3]), "r"(b[0]), "r"(b[1]));
}
// pack truncated-hi halves of (a,b): low bf16 = a.hi16, high bf16 = b.hi16
__device__ __forceinline__ uint32_t pack_hi2(float a, float b) {
    uint32_t r;
    asm("prmt.b32 %0, %1, %2, 0x7632;" : "=r"(r)
        : "r"(__float_as_uint(a)), "r"(__float_as_uint(b)));
    return r;
}
// pack residuals (a - trunc(a), b - trunc(b)) as bf16x2, a in low half
__device__ __forceinline__ uint32_t pack_lo2(float a, float b) {
    float la = a - __uint_as_float(__float_as_uint(a) & 0xFFFF0000u);
    float lb = b - __uint_as_float(__float_as_uint(b) & 0xFFFF0000u);
    uint32_t r;
    asm("cvt.rn.bf16x2.f32 %0, %1, %2;" : "=r"(r) : "f"(lb), "f"(la));
    return r;
}

// ---------------------------------------------------------------------------
// fp32 -> bf16 hi/lo split (round-to-nearest based)
// ---------------------------------------------------------------------------
__global__ void split_f32(const float* __restrict__ x,
                          __nv_bfloat16* __restrict__ hi,
                          __nv_bfloat16* __restrict__ lo, int n)
{
    int i = blockIdx.x * blockDim.x + threadIdx.x;
    if (i < n) {
        float v = x[i];
        __nv_bfloat16 h = __float2bfloat16(v);
        hi[i] = h;
        lo[i] = __float2bfloat16(v - __bfloat162float(h));
    }
}

// Transpose + split: W[K][N] fp32 -> Thi/Tlo[N][K] bf16
__global__ void splitT_f32(const float* __restrict__ W,
                           __nv_bfloat16* __restrict__ Thi,
                           __nv_bfloat16* __restrict__ Tlo, int K, int N)
{
    __shared__ float t[32][33];
    int n0 = blockIdx.x * 32, k0 = blockIdx.y * 32;
    int tx = threadIdx.x, ty = threadIdx.y;   // 32 x 8
    for (int r = ty; r < 32; r += 8)
        t[r][tx] = W[(size_t)(k0 + r) * N + n0 + tx];
    __syncthreads();
    for (int r = ty; r < 32; r += 8) {
        float v = t[tx][r];
        __nv_bfloat16 h = __float2bfloat16(v);
        size_t o = (size_t)(n0 + r) * K + k0 + tx;
        Thi[o] = h;
        Tlo[o] = __float2bfloat16(v - __bfloat162float(h));
    }
}

// ---------------------------------------------------------------------------
// mma.sync bf16x3 GEMM:  C[M,N] = A[M,K] * B^T   (A,B stored [rows][K] bf16)
// If Chi != null: write bf16 trunc-hi/residual-lo pair instead of fp32.
// ---------------------------------------------------------------------------
#define BKSLAB     32
#define OPB        8192
#define STAGEB     (4 * OPB)
#define GSTAGES    3
#define GEMM_SMEM  (GSTAGES * STAGEB)   // 98304 B

__global__ void __launch_bounds__(256) gemm_mma(
    const __nv_bfloat16* __restrict__ Ahi, const __nv_bfloat16* __restrict__ Alo,
    const __nv_bfloat16* __restrict__ Bhi, const __nv_bfloat16* __restrict__ Blo,
    float* __restrict__ Cf, __nv_bfloat16* __restrict__ Chi,
    __nv_bfloat16* __restrict__ Clo, int N)
{
    extern __shared__ char smem[];
    const uint32_t sb = smem_u32(smem);
    const int tid  = threadIdx.x;
    const int m0   = blockIdx.y * 128;
    const int n0   = blockIdx.x * 128;
    const int wid  = tid >> 5, lane = tid & 31;
    const int warp_m = (wid & 1) * 64;
    const int warp_n = (wid >> 1) * 32;

    const __nv_bfloat16* pAh = Ahi + (size_t)m0 * K_;
    const __nv_bfloat16* pAl = Alo + (size_t)m0 * K_;
    const __nv_bfloat16* pBh = Bhi + (size_t)n0 * K_;
    const __nv_bfloat16* pBl = Blo + (size_t)n0 * K_;

    auto load_stage = [&](int it, int slot) {
        const uint32_t st = sb + slot * STAGEB;
        const int kb = it * BKSLAB;
#pragma unroll
        for (int i = 0; i < 8; i++) {
            const __nv_bfloat16* base = (i < 2) ? pAh : (i < 4) ? pAl : (i < 6) ? pBh : pBl;
            int w   = ((i & 1) << 8) + tid;
            int row = w >> 2;
            int k8  = w & 3;
            const void* src = base + (size_t)row * K_ + kb + k8 * 8;
            uint32_t dst = st + (i >> 1) * OPB + (k8 * 16 + (row >> 3)) * 128 + (row & 7) * 16;
            cpa16(dst, src);
        }
        asm volatile("cp.async.commit_group;" ::: "memory");
    };

    float acc[4][4][4];
#pragma unroll
    for (int a = 0; a < 4; a++)
#pragma unroll
        for (int b = 0; b < 4; b++)
#pragma unroll
            for (int c = 0; c < 4; c++) acc[a][b][c] = 0.f;

    const int mA  = warp_m + (lane & 15);
    const int mA8 = mA >> 3, mA7 = (mA & 7) * 16;
    const int k8A = lane >> 4;
    const int nB  = warp_n + ((lane >> 4) << 3) + (lane & 7);
    const int nB8 = nB >> 3, nB7 = (nB & 7) * 16;
    const int k8B = (lane >> 3) & 1;

    load_stage(0, 0);
    load_stage(1, 1);

    const int NIT = K_ / BKSLAB;
    for (int it = 0; it < NIT; it++) {
        if (it + 1 < NIT) asm volatile("cp.async.wait_group 1;" ::: "memory");
        else              asm volatile("cp.async.wait_group 0;" ::: "memory");
        __syncthreads();
        if (it + 2 < NIT) load_stage(it + 2, (it + 2) % GSTAGES);

        const uint32_t st = sb + (it % GSTAGES) * STAGEB;
        const uint32_t AH = st, AL = st + OPB, BH = st + 2 * OPB, BL = st + 3 * OPB;

#pragma unroll
        for (int ks = 0; ks < 2; ks++) {
            uint32_t ah[4][4], al[4][4], bb[4][2];
            const int kA = (ks * 2 + k8A) * 2048;
            const int kB = (ks * 2 + k8B) * 2048;
#pragma unroll
            for (int mt = 0; mt < 4; mt++)
                ldm4(ah[mt], AH + kA + (mA8 + mt * 2) * 128 + mA7);
#pragma unroll
            for (int j = 0; j < 2; j++)
                ldm4(&bb[j * 2][0], BH + kB + (nB8 + j * 2) * 128 + nB7);
#pragma unroll
            for (int mt = 0; mt < 4; mt++)
#pragma unroll
                for (int nt = 0; nt < 4; nt++) mma16816(acc[mt][nt], ah[mt], bb[nt]);
#pragma unroll
            for (int mt = 0; mt < 4; mt++)
                ldm4(al[mt], AL + kA + (mA8 + mt * 2) * 128 + mA7);
#pragma unroll
            for (int mt = 0; mt < 4; mt++)
#pragma unroll
                for (int nt = 0; nt < 4; nt++) mma16816(acc[mt][nt], al[mt], bb[nt]);
#pragma unroll
            for (int j = 0; j < 2; j++)
                ldm4(&bb[j * 2][0], BL + kB + (nB8 + j * 2) * 128 + nB7);
#pragma unroll
            for (int mt = 0; mt < 4; mt++)
#pragma unroll
                for (int nt = 0; nt < 4; nt++) mma16816(acc[mt][nt], ah[mt], bb[nt]);
        }
        __syncthreads();
    }

    const int r0 = m0 + warp_m + (lane >> 2);
    const int c0 = n0 + warp_n + (lane & 3) * 2;
    if (Chi) {
#pragma unroll
        for (int mt = 0; mt < 4; mt++) {
#pragma unroll
            for (int nt = 0; nt < 4; nt++) {
                size_t o0 = (size_t)(r0 + mt * 16) * N + c0 + nt * 8;
                size_t o1 = o0 + (size_t)8 * N;
                *(uint32_t*)(Chi + o0) = pack_hi2(acc[mt][nt][0], acc[mt][nt][1]);
                *(uint32_t*)(Clo + o0) = pack_lo2(acc[mt][nt][0], acc[mt][nt][1]);
                *(uint32_t*)(Chi + o1) = pack_hi2(acc[mt][nt][2], acc[mt][nt][3]);
                *(uint32_t*)(Clo + o1) = pack_lo2(acc[mt][nt][2], acc[mt][nt][3]);
            }
        }
    } else {
#pragma unroll
        for (int mt = 0; mt < 4; mt++) {
#pragma unroll
            for (int nt = 0; nt < 4; nt++) {
                float* p = Cf + (size_t)(r0 + mt * 16) * N + c0 + nt * 8;
                *(float2*)p                   = make_float2(acc[mt][nt][0], acc[mt][nt][1]);
                *(float2*)(p + (size_t)8 * N) = make_float2(acc[mt][nt][2], acc[mt][nt][3]);
            }
        }
    }
}

// ---------------------------------------------------------------------------
// Tensor-core flash attention, split-bf16 x3, causal + ALiBi.
// CTA: 128 q-rows, 64 keys/iter, 8 warps (16 q-rows each), 2-stage cp.async.
// Scores in log2 domain; P split by truncation; PV via ldmatrix.trans on V.
// ---------------------------------------------------------------------------
#define AQT       128
#define AKT       64
#define AOPB      8192                   // 64 rows x 64 bf16 x 2B
#define ASTAGEB   (4 * AOPB)             // Kh,Kl,Vh,Vl
#define ATT_SMEM  (32768 + 2 * ASTAGEB)  // Qh+Ql + 2 stages = 98304 B

__global__ void __launch_bounds__(256, 2) attn_mma(
    const __nv_bfloat16* __restrict__ qkvh, const __nv_bfloat16* __restrict__ qkvl,
    __nv_bfloat16* __restrict__ oh, __nv_bfloat16* __restrict__ ol)
{
    extern __shared__ char smem[];
    const uint32_t sb = smem_u32(smem);
    const uint32_t Qh = sb, Ql = sb + 16384;
    const uint32_t ST0 = sb + 32768;

    const int tid  = threadIdx.x;
    const int wid  = tid >> 5, lane = tid & 31;
    const int b    = blockIdx.z;
    const int h    = blockIdx.y;
    const int qt   = blockIdx.x;
    const int q0   = qt * AQT;
    const int nkt  = 2 * qt + 2;
    const size_t rbase = (size_t)b * T_;   // row offset into [M][3C]

    const float LOG2E = 1.4426950408889634f;
    const float sc2 = LOG2E / 32.0f;
    const float sl2 = exp2f(-0.5f * (float)(h + 1)) * LOG2E;

    // ---- load Q tile (hi+lo): 128 rows x 8 chunks x 2 = 2048 cp.async
    for (int i = tid; i < 2048; i += 256) {
        int arr = i >> 10, r = (i >> 3) & 127, c8 = i & 7;
        const __nv_bfloat16* g = arr ? qkvl : qkvh;
        const void* src = g + (rbase + q0 + r) * C3_ + h * DH_ + c8 * 8;
        uint32_t dst = (arr ? Ql : Qh) + (c8 * 16 + (r >> 3)) * 128 + (r & 7) * 16;
        cpa16(dst, src);
    }
    auto load_stage = [&](int kt, int slot) {
        const int k0 = kt * AKT;
        const uint32_t st = ST0 + slot * ASTAGEB;
        for (int i = tid; i < 2048; i += 256) {
            int op = i >> 9, r = (i >> 3) & 63, c8 = i & 7;
            const __nv_bfloat16* g = (op & 1) ? qkvl : qkvh;
            int coloff = ((op < 2) ? C_ : 2 * C_) + h * DH_;
            const void* src = g + (rbase + k0 + r) * C3_ + coloff + c8 * 8;
            uint32_t dst = st + op * AOPB + (c8 * 8 + (r >> 3)) * 128 + (r & 7) * 16;
            cpa16(dst, src);
        }
        asm volatile("cp.async.commit_group;" ::: "memory");
    };
    load_stage(0, 0);   // group 0 = Q + stage 0

    // ---- per-thread state
    float oacc[8][4];
#pragma unroll
    for (int j = 0; j < 8; j++)
#pragma unroll
        for (int c = 0; c < 4; c++) oacc[j][c] = 0.f;
    float m0r = -1e30f, m1r = -1e30f, l0 = 0.f, l1 = 0.f;

    const int rA   = wid * 16 + (lane & 15);         // Q ldmatrix row
    const int rA8  = rA >> 3, rA7 = (rA & 7) * 16;
    const int qc8h = lane >> 4;                      // Q k-chunk half
    const int nKl  = (lane & 7) + ((lane >> 4) << 3);// K ldmatrix row-in-group
    const int kc8h = (lane >> 3) & 1;                // K k-chunk half
    const int rVl  = (lane & 7) + (((lane >> 3) & 1) << 3); // V trans row-in-group
    const int vc8h = lane >> 4;                      // V n-chunk half
    const int row0 = q0 + wid * 16 + (lane >> 2);    // softmax rows
    const int row1 = row0 + 8;

    for (int kt = 0; kt < nkt; kt++) {
        if (kt + 1 < nkt) load_stage(kt + 1, (kt + 1) & 1);
        if (kt + 1 < nkt) asm volatile("cp.async.wait_group 1;" ::: "memory");
        else              asm volatile("cp.async.wait_group 0;" ::: "memory");
        __syncthreads();

        const int k0 = kt * AKT;
        const uint32_t st = ST0 + (kt & 1) * ASTAGEB;
        const uint32_t Kh = st, Kl = st + AOPB, Vh = st + 2 * AOPB, Vl = st + 3 * AOPB;

        // ---- scores: sacc = Qh*Kh + Qh*Kl + Ql*Kh
        float sacc[8][4];
#pragma unroll
        for (int j = 0; j < 8; j++)
#pragma unroll
            for (int c = 0; c < 4; c++) sacc[j][c] = 0.f;

#pragma unroll
        for (int ks = 0; ks < 4; ks++) {
            uint32_t qfh[4], qfl[4];
            const uint32_t qoff = ((2 * ks + qc8h) * 16 + rA8) * 128 + rA7;
            ldm4(qfh, Qh + qoff);
            ldm4(qfl, Ql + qoff);
#pragma unroll
            for (int j = 0; j < 4; j++) {
                uint32_t kfh[4], kfl[4];
                const int rowK = 16 * j + nKl;
                const uint32_t koff = ((2 * ks + kc8h) * 8 + (rowK >> 3)) * 128 + (rowK & 7) * 16;
                ldm4(kfh, Kh + koff);
                ldm4(kfl, Kl + koff);
                mma16816(sacc[2 * j],     qfh, kfh);
                mma16816(sacc[2 * j + 1], qfh, kfh + 2);
                mma16816(sacc[2 * j],     qfh, kfl);
                mma16816(sacc[2 * j + 1], qfh, kfl + 2);
                mma16816(sacc[2 * j],     qfl, kfh);
                mma16816(sacc[2 * j + 1], qfl, kfh + 2);
            }
        }

        // ---- softmax (log2 domain): scale + alibi + causal, running max/sum
        float mx0 = -1e30f, mx1 = -1e30f;
#pragma unroll
        for (int j = 0; j < 8; j++) {
            int col = k0 + j * 8 + (lane & 3) * 2;
            float s0 = (col     <= row0) ? sacc[j][0] * sc2 + sl2 * (float)(col     - row0) : -1e30f;
            float s1 = (col + 1 <= row0) ? sacc[j][1] * sc2 + sl2 * (float)(col + 1 - row0) : -1e30f;
            float s2 = (col     <= row1) ? sacc[j][2] * sc2 + sl2 * (float)(col     - row1) : -1e30f;
            float s3 = (col + 1 <= row1) ? sacc[j][3] * sc2 + sl2 * (float)(col + 1 - row1) : -1e30f;
            sacc[j][0] = s0; sacc[j][1] = s1; sacc[j][2] = s2; sacc[j][3] = s3;
            mx0 = fmaxf(mx0, fmaxf(s0, s1));
            mx1 = fmaxf(mx1, fmaxf(s2, s3));
        }
        mx0 = fmaxf(mx0, __shfl_xor_sync(0xFFFFFFFFu, mx0, 1));
        mx0 = fmaxf(mx0, __shfl_xor_sync(0xFFFFFFFFu, mx0, 2));
        mx1 = fmaxf(mx1, __shfl_xor_sync(0xFFFFFFFFu, mx1, 1));
        mx1 = fmaxf(mx1, __shfl_xor_sync(0xFFFFFFFFu, mx1, 2));
        float mn0 = fmaxf(m0r, mx0), mn1 = fmaxf(m1r, mx1);
        float cr0 = exp2f(m0r - mn0), cr1 = exp2f(m1r - mn1);
        m0r = mn0; m1r = mn1;
        l0 *= cr0; l1 *= cr1;
#pragma unroll
        for (int j = 0; j < 8; j++) {
            float p0 = exp2f(sacc[j][0] - mn0);
            float p1 = exp2f(sacc[j][1] - mn0);
            float p2 = exp2f(sacc[j][2] - mn1);
            float p3 = exp2f(sacc[j][3] - mn1);
            l0 += p0 + p1; l1 += p2 + p3;
            sacc[j][0] = p0; sacc[j][1] = p1; sacc[j][2] = p2; sacc[j][3] = p3;
        }
#pragma unroll
        for (int j = 0; j < 8; j++) {
            oacc[j][0] *= cr0; oacc[j][1] *= cr0;
            oacc[j][2] *= cr1; oacc[j][3] *= cr1;
        }

        // ---- P fragments (trunc-hi / residual-lo), recast C->A layout
        uint32_t pah[4][4], pal[4][4];
#pragma unroll
        for (int t = 0; t < 4; t++) {
            pah[t][0] = pack_hi2(sacc[2 * t][0],     sacc[2 * t][1]);
            pah[t][1] = pack_hi2(sacc[2 * t][2],     sacc[2 * t][3]);
            pah[t][2] = pack_hi2(sacc[2 * t + 1][0], sacc[2 * t + 1][1]);
            pah[t][3] = pack_hi2(sacc[2 * t + 1][2], sacc[2 * t + 1][3]);
            pal[t][0] = pack_lo2(sacc[2 * t][0],     sacc[2 * t][1]);
            pal[t][1] = pack_lo2(sacc[2 * t][2],     sacc[2 * t][3]);
            pal[t][2] = pack_lo2(sacc[2 * t + 1][0], sacc[2 * t + 1][1]);
            pal[t][3] = pack_lo2(sacc[2 * t + 1][2], sacc[2 * t + 1][3]);
        }

        // ---- O += P * V  (Ph*Vh + Ph*Vl + Pl*Vh), V via ldmatrix.trans
#pragma unroll
        for (int g = 0; g < 4; g++) {
#pragma unroll
            for (int ks = 0; ks < 4; ks++) {
                uint32_t vfh[4], vfl[4];
                const int rowV = 16 * ks + rVl;
                const uint32_t voff = ((2 * g + vc8h) * 8 + (rowV >> 3)) * 128 + (rowV & 7) * 16;
                ldm4t(vfh, Vh + voff);
                ldm4t(vfl, Vl + voff);
                mma16816(oacc[2 * g],     pah[ks], vfh);
                mma16816(oacc[2 * g + 1], pah[ks], vfh + 2);
                mma16816(oacc[2 * g],     pah[ks], vfl);
                mma16816(oacc[2 * g + 1], pah[ks], vfl + 2);
                mma16816(oacc[2 * g],     pal[ks], vfh);
                mma16816(oacc[2 * g + 1], pal[ks], vfh + 2);
            }
        }
        __syncthreads();
    }

    // ---- epilogue: normalize, split, store bf16 hi/lo
    l0 += __shfl_xor_sync(0xFFFFFFFFu, l0, 1);
    l0 += __shfl_xor_sync(0xFFFFFFFFu, l0, 2);
    l1 += __shfl_xor_sync(0xFFFFFFFFu, l1, 1);
    l1 += __shfl_xor_sync(0xFFFFFFFFu, l1, 2);
    const float iv0 = 1.0f / l0, iv1 = 1.0f / l1;
    const size_t gr0 = (rbase + row0) * C_;
    const size_t gr1 = (rbase + row1) * C_;
#pragma unroll
    for (int j = 0; j < 8; j++) {
        int col = h * DH_ + j * 8 + (lane & 3) * 2;
        float o0 = oacc[j][0] * iv0, o1 = oacc[j][1] * iv0;
        float o2 = oacc[j][2] * iv1, o3 = oacc[j][3] * iv1;
        *(uint32_t*)(oh + gr0 + col) = pack_hi2(o0, o1);
        *(uint32_t*)(ol + gr0 + col) = pack_lo2(o0, o1);
        *(uint32_t*)(oh + gr1 + col) = pack_hi2(o2, o3);
        *(uint32_t*)(ol + gr1 + col) = pack_lo2(o2, o3);
    }
}

// ---------------------------------------------------------------------------
extern "C" void kernel_launch(void* const* d_in, const int* in_sizes, int n_in,
                              void* d_out, int out_size)
{
    const float* x     = (const float*)d_in[0];
    const float* w_qkv = (const float*)d_in[1];
    const float* w_o   = (const float*)d_in[2];
    float* out = (float*)d_out;

    __nv_bfloat16 *xhi, *xlo, *qkvh, *qkvl, *wqhi, *wqlo, *wohi, *wolo;
    cudaGetSymbolAddress((void**)&xhi,  g_xhi);
    cudaGetSymbolAddress((void**)&xlo,  g_xlo);
    cudaGetSymbolAddress((void**)&qkvh, g_qkvh);
    cudaGetSymbolAddress((void**)&qkvl, g_qkvl);
    cudaGetSymbolAddress((void**)&wqhi, g_wqhi);
    cudaGetSymbolAddress((void**)&wqlo, g_wqlo);
    cudaGetSymbolAddress((void**)&wohi, g_wohi);
    cudaGetSymbolAddress((void**)&wolo, g_wolo);

    cudaFuncSetAttribute(gemm_mma, cudaFuncAttributeMaxDynamicSharedMemorySize, GEMM_SMEM);
    cudaFuncSetAttribute(attn_mma, cudaFuncAttributeMaxDynamicSharedMemorySize, ATT_SMEM);

    // 0) input / weight splits
    split_f32<<<(M_ * C_ + 255) / 256, 256>>>(x, xhi, xlo, M_ * C_);
    splitT_f32<<<dim3(C3_ / 32, C_ / 32), dim3(32, 8)>>>(w_qkv, wqhi, wqlo, C_, C3_);
    splitT_f32<<<dim3(C_ / 32,  C_ / 32), dim3(32, 8)>>>(w_o,   wohi, wolo, C_, C_);

    // 1) qkv = x @ w_qkv  -> bf16 hi/lo directly
    gemm_mma<<<dim3(C3_ / 128, M_ / 128), 256, GEMM_SMEM>>>(
        xhi, xlo, wqhi, wqlo, nullptr, qkvh, qkvl, C3_);

    // 2) tensor-core flash attention -> bf16 hi/lo (reuse xhi/xlo)
    attn_mma<<<dim3(T_ / AQT, H_, B_), 256, ATT_SMEM>>>(qkvh, qkvl, xhi, xlo);

    // 3) out = attn @ w_o  (fp32 out)
    gemm_mma<<<dim3(C_ / 128, M_ / 128), 256, GEMM_SMEM>>>(
        xhi, xlo, wohi, wolo, out, nullptr, nullptr, C_);
}

// round 6
// speedup vs baseline: 2.0904x; 1.0627x over previous
#include <cuda_runtime.h>
#include <cuda_bf16.h>
#include <cstdint>

#define B_   4
#define T_   2048
#define C_   1024
#define H_   16
#define DH_  64
#define C3_  3072
#define M_   (B_*T_)      // 8192 rows
#define K_   1024

// ---------------------------------------------------------------------------
// Scratch (no cudaMalloc). xhi/xlo are reused for the attention bf16 output
// (x-split dead after GEMM-1; attention writes only after it retires).
// ---------------------------------------------------------------------------
__device__ __nv_bfloat16 g_xhi[(size_t)M_ * C_];
__device__ __nv_bfloat16 g_xlo[(size_t)M_ * C_];
__device__ __nv_bfloat16 g_qkvh[(size_t)M_ * C3_];   // qkv hi  [M][3C]
__device__ __nv_bfloat16 g_qkvl[(size_t)M_ * C3_];   // qkv lo
__device__ __nv_bfloat16 g_wqhi[(size_t)C3_ * C_];   // W_qkv^T [3072][1024]
__device__ __nv_bfloat16 g_wqlo[(size_t)C3_ * C_];
__device__ __nv_bfloat16 g_wohi[(size_t)C_ * C_];    // W_o^T   [1024][1024]
__device__ __nv_bfloat16 g_wolo[(size_t)C_ * C_];

// ---------------------------------------------------------------------------
// Helpers (plain compute_103-legal)
// ---------------------------------------------------------------------------
__device__ __forceinline__ uint32_t smem_u32(const void* p) {
    uint32_t a;
    asm("{ .reg .u64 t; cvta.to.shared.u64 t, %1; cvt.u32.u64 %0, t; }" : "=r"(a) : "l"(p));
    return a;
}
__device__ __forceinline__ void cpa16(uint32_t dst, const void* src) {
    asm volatile("cp.async.cg.shared.global [%0], [%1], 16;" :: "r"(dst), "l"(src));
}
__device__ __forceinline__ void ldm4(uint32_t* r, uint32_t addr) {
    asm volatile("ldmatrix.sync.aligned.m8n8.x4.shared.b16 {%0,%1,%2,%3}, [%4];"
                 : "=r"(r[0]), "=r"(r[1]), "=r"(r[2]), "=r"(r[3]) : "r"(addr));
}
__device__ __forceinline__ void ldm4t(uint32_t* r, uint32_t addr) {
    asm volatile("ldmatrix.sync.aligned.m8n8.x4.trans.shared.b16 {%0,%1,%2,%3}, [%4];"
                 : "=r"(r[0]), "=r"(r[1]), "=r"(r[2]), "=r"(r[3]) : "r"(addr));
}
__device__ __forceinline__ void mma16816(float* d, const uint32_t* a, const uint32_t* b) {
    asm volatile("mma.sync.aligned.m16n8k16.row.col.f32.bf16.bf16.f32 "
                 "{%0,%1,%2,%3}, {%4,%5,%6,%7}, {%8,%9}, {%0,%1,%2,%3};"
                 : "+f"(d[0]), "+f"(d[1]), "+f"(d[2]), "+f"(d[3])
                 : "r"(a[0]), "r"(a[1]), "r"(a[2]), "r"(a[3]), "r"(b[0]), "r"(b[1]));
}
// pack truncated-hi halves of (a,b): low bf16 = a.hi16, high bf16 = b.hi16
__device__ __forceinline__ uint32_t pack_hi2(float a, float b) {
    uint32_t r;
    asm("prmt.b32 %0, %1, %2, 0x7632;" : "=r"(r)
        : "r"(__float_as_uint(a)), "r"(__float_as_uint(b)));
    return r;
}
// pack residuals (a - trunc(a), b - trunc(b)) as bf16x2, a in low half
__device__ __forceinline__ uint32_t pack_lo2(float a, float b) {
    float la = a - __uint_as_float(__float_as_uint(a) & 0xFFFF0000u);
    float lb = b - __uint_as_float(__float_as_uint(b) & 0xFFFF0000u);
    uint32_t r;
    asm("cvt.rn.bf16x2.f32 %0, %1, %2;" : "=r"(r) : "f"(lb), "f"(la));
    return r;
}

// ---------------------------------------------------------------------------
// fp32 -> bf16 hi/lo split
// ---------------------------------------------------------------------------
__global__ void split_f32(const float* __restrict__ x,
                          __nv_bfloat16* __restrict__ hi,
                          __nv_bfloat16* __restrict__ lo, int n)
{
    int i = blockIdx.x * blockDim.x + threadIdx.x;
    if (i < n) {
        float v = x[i];
        __nv_bfloat16 h = __float2bfloat16(v);
        hi[i] = h;
        lo[i] = __float2bfloat16(v - __bfloat162float(h));
    }
}

// Transpose + split: W[K][N] fp32 -> Thi/Tlo[N][K] bf16
__global__ void splitT_f32(const float* __restrict__ W,
                           __nv_bfloat16* __restrict__ Thi,
                           __nv_bfloat16* __restrict__ Tlo, int K, int N)
{
    __shared__ float t[32][33];
    int n0 = blockIdx.x * 32, k0 = blockIdx.y * 32;
    int tx = threadIdx.x, ty = threadIdx.y;   // 32 x 8
    for (int r = ty; r < 32; r += 8)
        t[r][tx] = W[(size_t)(k0 + r) * N + n0 + tx];
    __syncthreads();
    for (int r = ty; r < 32; r += 8) {
        float v = t[tx][r];
        __nv_bfloat16 h = __float2bfloat16(v);
        size_t o = (size_t)(n0 + r) * K + k0 + tx;
        Thi[o] = h;
        Tlo[o] = __float2bfloat16(v - __bfloat162float(h));
    }
}

// ---------------------------------------------------------------------------
// mma.sync bf16x3 GEMM:  C[M,N] = A[M,K] * B^T   (A,B stored [rows][K] bf16)
// __launch_bounds__(256,2): cap 128 regs/thread for 2 CTAs/SM.
// Inner loop restructured for low live pressure:
//   hold ah(16)+bb(8); Al pass streams one 4-reg frag per m-stripe;
//   BL pass overwrites the BH fragment registers.
// ---------------------------------------------------------------------------
#define BKSLAB     32
#define OPB        8192
#define STAGEB     (4 * OPB)
#define GSTAGES    3
#define GEMM_SMEM  (GSTAGES * STAGEB)   // 98304 B

__global__ void __launch_bounds__(256, 2) gemm_mma(
    const __nv_bfloat16* __restrict__ Ahi, const __nv_bfloat16* __restrict__ Alo,
    const __nv_bfloat16* __restrict__ Bhi, const __nv_bfloat16* __restrict__ Blo,
    float* __restrict__ Cf, __nv_bfloat16* __restrict__ Chi,
    __nv_bfloat16* __restrict__ Clo, int N)
{
    extern __shared__ char smem[];
    const uint32_t sb = smem_u32(smem);
    const int tid  = threadIdx.x;
    const int m0   = blockIdx.y * 128;
    const int n0   = blockIdx.x * 128;
    const int wid  = tid >> 5, lane = tid & 31;
    const int warp_m = (wid & 1) * 64;
    const int warp_n = (wid >> 1) * 32;

    const __nv_bfloat16* pAh = Ahi + (size_t)m0 * K_;
    const __nv_bfloat16* pAl = Alo + (size_t)m0 * K_;
    const __nv_bfloat16* pBh = Bhi + (size_t)n0 * K_;
    const __nv_bfloat16* pBl = Blo + (size_t)n0 * K_;

    auto load_stage = [&](int it, int slot) {
        const uint32_t st = sb + slot * STAGEB;
        const int kb = it * BKSLAB;
#pragma unroll
        for (int i = 0; i < 8; i++) {
            const __nv_bfloat16* base = (i < 2) ? pAh : (i < 4) ? pAl : (i < 6) ? pBh : pBl;
            int w   = ((i & 1) << 8) + tid;
            int row = w >> 2;
            int k8  = w & 3;
            const void* src = base + (size_t)row * K_ + kb + k8 * 8;
            uint32_t dst = st + (i >> 1) * OPB + (k8 * 16 + (row >> 3)) * 128 + (row & 7) * 16;
            cpa16(dst, src);
        }
        asm volatile("cp.async.commit_group;" ::: "memory");
    };

    float acc[4][4][4];
#pragma unroll
    for (int a = 0; a < 4; a++)
#pragma unroll
        for (int b = 0; b < 4; b++)
#pragma unroll
            for (int c = 0; c < 4; c++) acc[a][b][c] = 0.f;

    const int mA  = warp_m + (lane & 15);
    const int mA8 = mA >> 3, mA7 = (mA & 7) * 16;
    const int k8A = lane >> 4;
    const int nB  = warp_n + ((lane >> 4) << 3) + (lane & 7);
    const int nB8 = nB >> 3, nB7 = (nB & 7) * 16;
    const int k8B = (lane >> 3) & 1;

    load_stage(0, 0);
    load_stage(1, 1);

    const int NIT = K_ / BKSLAB;
    for (int it = 0; it < NIT; it++) {
        if (it + 1 < NIT) asm volatile("cp.async.wait_group 1;" ::: "memory");
        else              asm volatile("cp.async.wait_group 0;" ::: "memory");
        __syncthreads();
        if (it + 2 < NIT) load_stage(it + 2, (it + 2) % GSTAGES);

        const uint32_t st = sb + (it % GSTAGES) * STAGEB;
        const uint32_t AH = st, AL = st + OPB, BH = st + 2 * OPB, BL = st + 3 * OPB;

#pragma unroll
        for (int ks = 0; ks < 2; ks++) {
            uint32_t ah[4][4], bb[4][2];
            const int kA = (ks * 2 + k8A) * 2048;
            const int kB = (ks * 2 + k8B) * 2048;
#pragma unroll
            for (int mt = 0; mt < 4; mt++)
                ldm4(ah[mt], AH + kA + (mA8 + mt * 2) * 128 + mA7);
#pragma unroll
            for (int j = 0; j < 2; j++)
                ldm4(&bb[j * 2][0], BH + kB + (nB8 + j * 2) * 128 + nB7);
            // Ah x Bh
#pragma unroll
            for (int mt = 0; mt < 4; mt++)
#pragma unroll
                for (int nt = 0; nt < 4; nt++) mma16816(acc[mt][nt], ah[mt], bb[nt]);
            // Al x Bh — stream one 4-reg Al fragment per m-stripe
#pragma unroll
            for (int mt = 0; mt < 4; mt++) {
                uint32_t al[4];
                ldm4(al, AL + kA + (mA8 + mt * 2) * 128 + mA7);
#pragma unroll
                for (int nt = 0; nt < 4; nt++) mma16816(acc[mt][nt], al, bb[nt]);
            }
            // Ah x Bl — overwrite BH fragment registers with BL
#pragma unroll
            for (int j = 0; j < 2; j++)
                ldm4(&bb[j * 2][0], BL + kB + (nB8 + j * 2) * 128 + nB7);
#pragma unroll
            for (int mt = 0; mt < 4; mt++)
#pragma unroll
                for (int nt = 0; nt < 4; nt++) mma16816(acc[mt][nt], ah[mt], bb[nt]);
        }
        __syncthreads();
    }

    const int r0 = m0 + warp_m + (lane >> 2);
    const int c0 = n0 + warp_n + (lane & 3) * 2;
    if (Chi) {
#pragma unroll
        for (int mt = 0; mt < 4; mt++) {
#pragma unroll
            for (int nt = 0; nt < 4; nt++) {
                size_t o0 = (size_t)(r0 + mt * 16) * N + c0 + nt * 8;
                size_t o1 = o0 + (size_t)8 * N;
                *(uint32_t*)(Chi + o0) = pack_hi2(acc[mt][nt][0], acc[mt][nt][1]);
                *(uint32_t*)(Clo + o0) = pack_lo2(acc[mt][nt][0], acc[mt][nt][1]);
                *(uint32_t*)(Chi + o1) = pack_hi2(acc[mt][nt][2], acc[mt][nt][3]);
                *(uint32_t*)(Clo + o1) = pack_lo2(acc[mt][nt][2], acc[mt][nt][3]);
            }
        }
    } else {
#pragma unroll
        for (int mt = 0; mt < 4; mt++) {
#pragma unroll
            for (int nt = 0; nt < 4; nt++) {
                float* p = Cf + (size_t)(r0 + mt * 16) * N + c0 + nt * 8;
                *(float2*)p                   = make_float2(acc[mt][nt][0], acc[mt][nt][1]);
                *(float2*)(p + (size_t)8 * N) = make_float2(acc[mt][nt][2], acc[mt][nt][3]);
            }
        }
    }
}

// ---------------------------------------------------------------------------
// Tensor-core flash attention, split-bf16 x3, causal + ALiBi (unchanged).
// ---------------------------------------------------------------------------
#define AQT       128
#define AKT       64
#define AOPB      8192                   // 64 rows x 64 bf16 x 2B
#define ASTAGEB   (4 * AOPB)             // Kh,Kl,Vh,Vl
#define ATT_SMEM  (32768 + 2 * ASTAGEB)  // Qh+Ql + 2 stages = 98304 B

__global__ void __launch_bounds__(256, 2) attn_mma(
    const __nv_bfloat16* __restrict__ qkvh, const __nv_bfloat16* __restrict__ qkvl,
    __nv_bfloat16* __restrict__ oh, __nv_bfloat16* __restrict__ ol)
{
    extern __shared__ char smem[];
    const uint32_t sb = smem_u32(smem);
    const uint32_t Qh = sb, Ql = sb + 16384;
    const uint32_t ST0 = sb + 32768;

    const int tid  = threadIdx.x;
    const int wid  = tid >> 5, lane = tid & 31;
    const int b    = blockIdx.z;
    const int h    = blockIdx.y;
    const int qt   = blockIdx.x;
    const int q0   = qt * AQT;
    const int nkt  = 2 * qt + 2;
    const size_t rbase = (size_t)b * T_;

    const float LOG2E = 1.4426950408889634f;
    const float sc2 = LOG2E / 32.0f;
    const float sl2 = exp2f(-0.5f * (float)(h + 1)) * LOG2E;

    for (int i = tid; i < 2048; i += 256) {
        int arr = i >> 10, r = (i >> 3) & 127, c8 = i & 7;
        const __nv_bfloat16* g = arr ? qkvl : qkvh;
        const void* src = g + (rbase + q0 + r) * C3_ + h * DH_ + c8 * 8;
        uint32_t dst = (arr ? Ql : Qh) + (c8 * 16 + (r >> 3)) * 128 + (r & 7) * 16;
        cpa16(dst, src);
    }
    auto load_stage = [&](int kt, int slot) {
        const int k0 = kt * AKT;
        const uint32_t st = ST0 + slot * ASTAGEB;
        for (int i = tid; i < 2048; i += 256) {
            int op = i >> 9, r = (i >> 3) & 63, c8 = i & 7;
            const __nv_bfloat16* g = (op & 1) ? qkvl : qkvh;
            int coloff = ((op < 2) ? C_ : 2 * C_) + h * DH_;
            const void* src = g + (rbase + k0 + r) * C3_ + coloff + c8 * 8;
            uint32_t dst = st + op * AOPB + (c8 * 8 + (r >> 3)) * 128 + (r & 7) * 16;
            cpa16(dst, src);
        }
        asm volatile("cp.async.commit_group;" ::: "memory");
    };
    load_stage(0, 0);

    float oacc[8][4];
#pragma unroll
    for (int j = 0; j < 8; j++)
#pragma unroll
        for (int c = 0; c < 4; c++) oacc[j][c] = 0.f;
    float m0r = -1e30f, m1r = -1e30f, l0 = 0.f, l1 = 0.f;

    const int rA   = wid * 16 + (lane & 15);
    const int rA8  = rA >> 3, rA7 = (rA & 7) * 16;
    const int qc8h = lane >> 4;
    const int nKl  = (lane & 7) + ((lane >> 4) << 3);
    const int kc8h = (lane >> 3) & 1;
    const int rVl  = (lane & 7) + (((lane >> 3) & 1) << 3);
    const int vc8h = lane >> 4;
    const int row0 = q0 + wid * 16 + (lane >> 2);
    const int row1 = row0 + 8;

    for (int kt = 0; kt < nkt; kt++) {
        if (kt + 1 < nkt) load_stage(kt + 1, (kt + 1) & 1);
        if (kt + 1 < nkt) asm volatile("cp.async.wait_group 1;" ::: "memory");
        else              asm volatile("cp.async.wait_group 0;" ::: "memory");
        __syncthreads();

        const int k0 = kt * AKT;
        const uint32_t st = ST0 + (kt & 1) * ASTAGEB;
        const uint32_t Kh = st, Kl = st + AOPB, Vh = st + 2 * AOPB, Vl = st + 3 * AOPB;

        float sacc[8][4];
#pragma unroll
        for (int j = 0; j < 8; j++)
#pragma unroll
            for (int c = 0; c < 4; c++) sacc[j][c] = 0.f;

#pragma unroll
        for (int ks = 0; ks < 4; ks++) {
            uint32_t qfh[4], qfl[4];
            const uint32_t qoff = ((2 * ks + qc8h) * 16 + rA8) * 128 + rA7;
            ldm4(qfh, Qh + qoff);
            ldm4(qfl, Ql + qoff);
#pragma unroll
            for (int j = 0; j < 4; j++) {
                uint32_t kfh[4], kfl[4];
                const int rowK = 16 * j + nKl;
                const uint32_t koff = ((2 * ks + kc8h) * 8 + (rowK >> 3)) * 128 + (rowK & 7) * 16;
                ldm4(kfh, Kh + koff);
                ldm4(kfl, Kl + koff);
                mma16816(sacc[2 * j],     qfh, kfh);
                mma16816(sacc[2 * j + 1], qfh, kfh + 2);
                mma16816(sacc[2 * j],     qfh, kfl);
                mma16816(sacc[2 * j + 1], qfh, kfl + 2);
                mma16816(sacc[2 * j],     qfl, kfh);
                mma16816(sacc[2 * j + 1], qfl, kfh + 2);
            }
        }

        float mx0 = -1e30f, mx1 = -1e30f;
#pragma unroll
        for (int j = 0; j < 8; j++) {
            int col = k0 + j * 8 + (lane & 3) * 2;
            float s0 = (col     <= row0) ? sacc[j][0] * sc2 + sl2 * (float)(col     - row0) : -1e30f;
            float s1 = (col + 1 <= row0) ? sacc[j][1] * sc2 + sl2 * (float)(col + 1 - row0) : -1e30f;
            float s2 = (col     <= row1) ? sacc[j][2] * sc2 + sl2 * (float)(col     - row1) : -1e30f;
            float s3 = (col + 1 <= row1) ? sacc[j][3] * sc2 + sl2 * (float)(col + 1 - row1) : -1e30f;
            sacc[j][0] = s0; sacc[j][1] = s1; sacc[j][2] = s2; sacc[j][3] = s3;
            mx0 = fmaxf(mx0, fmaxf(s0, s1));
            mx1 = fmaxf(mx1, fmaxf(s2, s3));
        }
        mx0 = fmaxf(mx0, __shfl_xor_sync(0xFFFFFFFFu, mx0, 1));
        mx0 = fmaxf(mx0, __shfl_xor_sync(0xFFFFFFFFu, mx0, 2));
        mx1 = fmaxf(mx1, __shfl_xor_sync(0xFFFFFFFFu, mx1, 1));
        mx1 = fmaxf(mx1, __shfl_xor_sync(0xFFFFFFFFu, mx1, 2));
        float mn0 = fmaxf(m0r, mx0), mn1 = fmaxf(m1r, mx1);
        float cr0 = exp2f(m0r - mn0), cr1 = exp2f(m1r - mn1);
        m0r = mn0; m1r = mn1;
        l0 *= cr0; l1 *= cr1;
#pragma unroll
        for (int j = 0; j < 8; j++) {
            float p0 = exp2f(sacc[j][0] - mn0);
            float p1 = exp2f(sacc[j][1] - mn0);
            float p2 = exp2f(sacc[j][2] - mn1);
            float p3 = exp2f(sacc[j][3] - mn1);
            l0 += p0 + p1; l1 += p2 + p3;
            sacc[j][0] = p0; sacc[j][1] = p1; sacc[j][2] = p2; sacc[j][3] = p3;
        }
#pragma unroll
        for (int j = 0; j < 8; j++) {
            oacc[j][0] *= cr0; oacc[j][1] *= cr0;
            oacc[j][2] *= cr1; oacc[j][3] *= cr1;
        }

        uint32_t pah[4][4], pal[4][4];
#pragma unroll
        for (int t = 0; t < 4; t++) {
            pah[t][0] = pack_hi2(sacc[2 * t][0],     sacc[2 * t][1]);
            pah[t][1] = pack_hi2(sacc[2 * t][2],     sacc[2 * t][3]);
            pah[t][2] = pack_hi2(sacc[2 * t + 1][0], sacc[2 * t + 1][1]);
            pah[t][3] = pack_hi2(sacc[2 * t + 1][2], sacc[2 * t + 1][3]);
            pal[t][0] = pack_lo2(sacc[2 * t][0],     sacc[2 * t][1]);
            pal[t][1] = pack_lo2(sacc[2 * t][2],     sacc[2 * t][3]);
            pal[t][2] = pack_lo2(sacc[2 * t + 1][0], sacc[2 * t + 1][1]);
            pal[t][3] = pack_lo2(sacc[2 * t + 1][2], sacc[2 * t + 1][3]);
        }

#pragma unroll
        for (int g = 0; g < 4; g++) {
#pragma unroll
            for (int ks = 0; ks < 4; ks++) {
                uint32_t vfh[4], vfl[4];
                const int rowV = 16 * ks + rVl;
                const uint32_t voff = ((2 * g + vc8h) * 8 + (rowV >> 3)) * 128 + (rowV & 7) * 16;
                ldm4t(vfh, Vh + voff);
                ldm4t(vfl, Vl + voff);
                mma16816(oacc[2 * g],     pah[ks], vfh);
                mma16816(oacc[2 * g + 1], pah[ks], vfh + 2);
                mma16816(oacc[2 * g],     pah[ks], vfl);
                mma16816(oacc[2 * g + 1], pah[ks], vfl + 2);
                mma16816(oacc[2 * g],     pal[ks], vfh);
                mma16816(oacc[2 * g + 1], pal[ks], vfh + 2);
            }
        }
        __syncthreads();
    }

    l0 += __shfl_xor_sync(0xFFFFFFFFu, l0, 1);
    l0 += __shfl_xor_sync(0xFFFFFFFFu, l0, 2);
    l1 += __shfl_xor_sync(0xFFFFFFFFu, l1, 1);
    l1 += __shfl_xor_sync(0xFFFFFFFFu, l1, 2);
    const float iv0 = 1.0f / l0, iv1 = 1.0f / l1;
    const size_t gr0 = (rbase + row0) * C_;
    const size_t gr1 = (rbase + row1) * C_;
#pragma unroll
    for (int j = 0; j < 8; j++) {
        int col = h * DH_ + j * 8 + (lane & 3) * 2;
        float o0 = oacc[j][0] * iv0, o1 = oacc[j][1] * iv0;
        float o2 = oacc[j][2] * iv1, o3 = oacc[j][3] * iv1;
        *(uint32_t*)(oh + gr0 + col) = pack_hi2(o0, o1);
        *(uint32_t*)(ol + gr0 + col) = pack_lo2(o0, o1);
        *(uint32_t*)(oh + gr1 + col) = pack_hi2(o2, o3);
        *(uint32_t*)(ol + gr1 + col) = pack_lo2(o2, o3);
    }
}

// ---------------------------------------------------------------------------
extern "C" void kernel_launch(void* const* d_in, const int* in_sizes, int n_in,
                              void* d_out, int out_size)
{
    const float* x     = (const float*)d_in[0];
    const float* w_qkv = (const float*)d_in[1];
    const float* w_o   = (const float*)d_in[2];
    float* out = (float*)d_out;

    __nv_bfloat16 *xhi, *xlo, *qkvh, *qkvl, *wqhi, *wqlo, *wohi, *wolo;
    cudaGetSymbolAddress((void**)&xhi,  g_xhi);
    cudaGetSymbolAddress((void**)&xlo,  g_xlo);
    cudaGetSymbolAddress((void**)&qkvh, g_qkvh);
    cudaGetSymbolAddress((void**)&qkvl, g_qkvl);
    cudaGetSymbolAddress((void**)&wqhi, g_wqhi);
    cudaGetSymbolAddress((void**)&wqlo, g_wqlo);
    cudaGetSymbolAddress((void**)&wohi, g_wohi);
    cudaGetSymbolAddress((void**)&wolo, g_wolo);

    cudaFuncSetAttribute(gemm_mma, cudaFuncAttributeMaxDynamicSharedMemorySize, GEMM_SMEM);
    cudaFuncSetAttribute(attn_mma, cudaFuncAttributeMaxDynamicSharedMemorySize, ATT_SMEM);

    // 0) input / weight splits
    split_f32<<<(M_ * C_ + 255) / 256, 256>>>(x, xhi, xlo, M_ * C_);
    splitT_f32<<<dim3(C3_ / 32, C_ / 32), dim3(32, 8)>>>(w_qkv, wqhi, wqlo, C_, C3_);
    splitT_f32<<<dim3(C_ / 32,  C_ / 32), dim3(32, 8)>>>(w_o,   wohi, wolo, C_, C_);

    // 1) qkv = x @ w_qkv  -> bf16 hi/lo directly
    gemm_mma<<<dim3(C3_ / 128, M_ / 128), 256, GEMM_SMEM>>>(
        xhi, xlo, wqhi, wqlo, nullptr, qkvh, qkvl, C3_);

    // 2) tensor-core flash attention -> bf16 hi/lo (reuse xhi/xlo)
    attn_mma<<<dim3(T_ / AQT, H_, B_), 256, ATT_SMEM>>>(qkvh, qkvl, xhi, xlo);

    // 3) out = attn @ w_o  (fp32 out)
    gemm_mma<<<dim3(C_ / 128, M_ / 128), 256, GEMM_SMEM>>>(
        xhi, xlo, wohi, wolo, out, nullptr, nullptr, C_);
}